// round 1
// baseline (speedup 1.0000x reference)
#include <cuda_runtime.h>
#include <math.h>

// Problem constants
#define NTOK 8192      // B*T
#define DIMD 1024
#define NEXP 8
#define HID  2816
#define NPAIR (2*NTOK) // top-2: every token produces exactly 2 (expert,token) pairs

// GEMM tiling
#define TM 64
#define TN 64
#define KB 32
#define LDA 68   // padded smem stride (floats); 68*4=272B keeps float4 rows 16B-aligned

// ---------------- device scratch (static: no allocations allowed) ----------------
__device__ float g_h[(size_t)NPAIR * HID];     // SwiGLU hidden per pair  (~176 MB)
__device__ float g_pout[(size_t)NPAIR * DIMD]; // per-pair output          (~64 MB)
__device__ int   g_list[NEXP * NTOK];          // per-expert packed slots (token*2+k)
__device__ float g_wt[NPAIR];                  // routing weight per slot
__device__ int   g_cnt[NEXP];                  // per-expert pair counts

// ---------------- packed f32x2 helpers ----------------
__device__ __forceinline__ unsigned long long ffma2(unsigned long long a,
                                                    unsigned long long b,
                                                    unsigned long long c) {
    unsigned long long d;
    asm("fma.rn.f32x2 %0, %1, %2, %3;" : "=l"(d) : "l"(a), "l"(b), "l"(c));
    return d;
}
__device__ __forceinline__ unsigned long long dup2(float a) {
    unsigned int u = __float_as_uint(a);
    return ((unsigned long long)u << 32) | (unsigned long long)u;
}
__device__ __forceinline__ float lo2(unsigned long long v) {
    return __uint_as_float((unsigned int)(v & 0xffffffffull));
}
__device__ __forceinline__ float hi2(unsigned long long v) {
    return __uint_as_float((unsigned int)(v >> 32));
}

// ---------------- kernels ----------------
__global__ void init_kernel() {
    if (threadIdx.x < NEXP) g_cnt[threadIdx.x] = 0;
}

// One warp per token: 8 router dots, softmax, top-2, renormalize, dispatch.
__global__ void router_kernel(const float* __restrict__ x,
                              const float* __restrict__ gw) {
    int w    = (blockIdx.x * blockDim.x + threadIdx.x) >> 5;
    int lane = threadIdx.x & 31;
    if (w >= NTOK) return;
    const float* xr = x + (size_t)w * DIMD;

    float acc[NEXP];
#pragma unroll
    for (int e = 0; e < NEXP; e++) acc[e] = 0.f;
    for (int d = lane; d < DIMD; d += 32) {
        float xv = xr[d];
#pragma unroll
        for (int e = 0; e < NEXP; e++) acc[e] += xv * gw[e * DIMD + d];
    }
#pragma unroll
    for (int e = 0; e < NEXP; e++)
#pragma unroll
        for (int o = 16; o > 0; o >>= 1)
            acc[e] += __shfl_xor_sync(0xffffffffu, acc[e], o);

    if (lane == 0) {
        float m = acc[0];
#pragma unroll
        for (int e = 1; e < NEXP; e++) m = fmaxf(m, acc[e]);
        float p[NEXP];
#pragma unroll
        for (int e = 0; e < NEXP; e++) p[e] = __expf(acc[e] - m);
        // top-2 (strict > keeps lower index on ties, matching jax top_k)
        int i0 = 0; float b0 = p[0];
#pragma unroll
        for (int e = 1; e < NEXP; e++) if (p[e] > b0) { b0 = p[e]; i0 = e; }
        int i1 = -1; float b1 = -1.f;
#pragma unroll
        for (int e = 0; e < NEXP; e++) if (e != i0 && p[e] > b1) { b1 = p[e]; i1 = e; }
        float s = b0 + b1;
        g_wt[2 * w]     = b0 / s;
        g_wt[2 * w + 1] = b1 / s;
        int pos0 = atomicAdd(&g_cnt[i0], 1);
        g_list[i0 * NTOK + pos0] = 2 * w;
        int pos1 = atomicAdd(&g_cnt[i1], 1);
        g_list[i1 * NTOK + pos1] = 2 * w + 1;
    }
}

// Stage A: h[slot, :] = silu(x@w1[e]^T) * (x@w3[e]^T) for this expert's tokens.
// NT GEMM: both A (x rows, gathered) and B (w rows) are K-contiguous.
__global__ __launch_bounds__(256) void ffn1_kernel(const float* __restrict__ x,
                                                   const float* __restrict__ w1,
                                                   const float* __restrict__ w3) {
    int e   = blockIdx.z;
    int cnt = g_cnt[e];
    int m0  = blockIdx.y * TM;
    if (m0 >= cnt) return;
    int n0  = blockIdx.x * TN;   // over HID

    __shared__ __align__(16) float As [KB][LDA];
    __shared__ __align__(16) float B1s[KB][LDA];
    __shared__ __align__(16) float B3s[KB][LDA];
    __shared__ int rows[TM];

    int tid = threadIdx.x;
    if (tid < TM) rows[tid] = g_list[e * NTOK + min(m0 + tid, cnt - 1)];
    __syncthreads();

    const float* W1 = w1 + (size_t)e * HID * DIMD;
    const float* W3 = w3 + (size_t)e * HID * DIMD;

    int tx = tid & 15, ty = tid >> 4;
    unsigned long long acc1[4][2], acc3[4][2];
#pragma unroll
    for (int i = 0; i < 4; i++)
#pragma unroll
        for (int j = 0; j < 2; j++) { acc1[i][j] = 0ull; acc3[i][j] = 0ull; }

    for (int k0 = 0; k0 < DIMD; k0 += KB) {
#pragma unroll
        for (int h = 0; h < 2; h++) {
            int idx = tid + h * 256;           // [0,512): 64 rows x 8 float4
            int r = idx >> 3, kq = (idx & 7) * 4;
            int tok = rows[r] >> 1;
            float4 av = *reinterpret_cast<const float4*>(x + (size_t)tok * DIMD + k0 + kq);
            As[kq + 0][r] = av.x; As[kq + 1][r] = av.y; As[kq + 2][r] = av.z; As[kq + 3][r] = av.w;
            float4 b1 = *reinterpret_cast<const float4*>(W1 + (size_t)(n0 + r) * DIMD + k0 + kq);
            B1s[kq + 0][r] = b1.x; B1s[kq + 1][r] = b1.y; B1s[kq + 2][r] = b1.z; B1s[kq + 3][r] = b1.w;
            float4 b3 = *reinterpret_cast<const float4*>(W3 + (size_t)(n0 + r) * DIMD + k0 + kq);
            B3s[kq + 0][r] = b3.x; B3s[kq + 1][r] = b3.y; B3s[kq + 2][r] = b3.z; B3s[kq + 3][r] = b3.w;
        }
        __syncthreads();
#pragma unroll
        for (int k = 0; k < KB; k++) {
            float4 av = *reinterpret_cast<const float4*>(&As[k][ty * 4]);
            ulonglong2 b1 = *reinterpret_cast<const ulonglong2*>(&B1s[k][tx * 4]);
            ulonglong2 b3 = *reinterpret_cast<const ulonglong2*>(&B3s[k][tx * 4]);
            unsigned long long ad0 = dup2(av.x), ad1 = dup2(av.y),
                               ad2 = dup2(av.z), ad3 = dup2(av.w);
            acc1[0][0] = ffma2(ad0, b1.x, acc1[0][0]); acc1[0][1] = ffma2(ad0, b1.y, acc1[0][1]);
            acc1[1][0] = ffma2(ad1, b1.x, acc1[1][0]); acc1[1][1] = ffma2(ad1, b1.y, acc1[1][1]);
            acc1[2][0] = ffma2(ad2, b1.x, acc1[2][0]); acc1[2][1] = ffma2(ad2, b1.y, acc1[2][1]);
            acc1[3][0] = ffma2(ad3, b1.x, acc1[3][0]); acc1[3][1] = ffma2(ad3, b1.y, acc1[3][1]);
            acc3[0][0] = ffma2(ad0, b3.x, acc3[0][0]); acc3[0][1] = ffma2(ad0, b3.y, acc3[0][1]);
            acc3[1][0] = ffma2(ad1, b3.x, acc3[1][0]); acc3[1][1] = ffma2(ad1, b3.y, acc3[1][1]);
            acc3[2][0] = ffma2(ad2, b3.x, acc3[2][0]); acc3[2][1] = ffma2(ad2, b3.y, acc3[2][1]);
            acc3[3][0] = ffma2(ad3, b3.x, acc3[3][0]); acc3[3][1] = ffma2(ad3, b3.y, acc3[3][1]);
        }
        __syncthreads();
    }

#pragma unroll
    for (int i = 0; i < 4; i++) {
        int mi = ty * 4 + i;
        if (m0 + mi < cnt) {
            int slot = rows[mi];
            float a1x = lo2(acc1[i][0]), a1y = hi2(acc1[i][0]);
            float a1z = lo2(acc1[i][1]), a1w = hi2(acc1[i][1]);
            float a3x = lo2(acc3[i][0]), a3y = hi2(acc3[i][0]);
            float a3z = lo2(acc3[i][1]), a3w = hi2(acc3[i][1]);
            float4 hv;
            hv.x = a1x / (1.f + __expf(-a1x)) * a3x;
            hv.y = a1y / (1.f + __expf(-a1y)) * a3y;
            hv.z = a1z / (1.f + __expf(-a1z)) * a3z;
            hv.w = a1w / (1.f + __expf(-a1w)) * a3w;
            *reinterpret_cast<float4*>(&g_h[(size_t)slot * HID + n0 + tx * 4]) = hv;
        }
    }
}

// Stage B: pout[slot, :] = (h[slot,:] @ w2[e]^T) * wt[slot].  K = HID.
__global__ __launch_bounds__(256) void ffn2_kernel(const float* __restrict__ w2) {
    int e   = blockIdx.z;
    int cnt = g_cnt[e];
    int m0  = blockIdx.y * TM;
    if (m0 >= cnt) return;
    int n0  = blockIdx.x * TN;   // over DIMD

    __shared__ __align__(16) float As[KB][LDA];
    __shared__ __align__(16) float Bs[KB][LDA];
    __shared__ int rows[TM];

    int tid = threadIdx.x;
    if (tid < TM) rows[tid] = g_list[e * NTOK + min(m0 + tid, cnt - 1)];
    __syncthreads();

    const float* W2 = w2 + (size_t)e * DIMD * HID;

    int tx = tid & 15, ty = tid >> 4;
    unsigned long long acc[4][2];
#pragma unroll
    for (int i = 0; i < 4; i++) { acc[i][0] = 0ull; acc[i][1] = 0ull; }

    for (int k0 = 0; k0 < HID; k0 += KB) {
#pragma unroll
        for (int h = 0; h < 2; h++) {
            int idx = tid + h * 256;
            int r = idx >> 3, kq = (idx & 7) * 4;
            int slot = rows[r];
            float4 av = *reinterpret_cast<const float4*>(&g_h[(size_t)slot * HID + k0 + kq]);
            As[kq + 0][r] = av.x; As[kq + 1][r] = av.y; As[kq + 2][r] = av.z; As[kq + 3][r] = av.w;
            float4 bv = *reinterpret_cast<const float4*>(W2 + (size_t)(n0 + r) * HID + k0 + kq);
            Bs[kq + 0][r] = bv.x; Bs[kq + 1][r] = bv.y; Bs[kq + 2][r] = bv.z; Bs[kq + 3][r] = bv.w;
        }
        __syncthreads();
#pragma unroll
        for (int k = 0; k < KB; k++) {
            float4 av = *reinterpret_cast<const float4*>(&As[k][ty * 4]);
            ulonglong2 bv = *reinterpret_cast<const ulonglong2*>(&Bs[k][tx * 4]);
            unsigned long long ad0 = dup2(av.x), ad1 = dup2(av.y),
                               ad2 = dup2(av.z), ad3 = dup2(av.w);
            acc[0][0] = ffma2(ad0, bv.x, acc[0][0]); acc[0][1] = ffma2(ad0, bv.y, acc[0][1]);
            acc[1][0] = ffma2(ad1, bv.x, acc[1][0]); acc[1][1] = ffma2(ad1, bv.y, acc[1][1]);
            acc[2][0] = ffma2(ad2, bv.x, acc[2][0]); acc[2][1] = ffma2(ad2, bv.y, acc[2][1]);
            acc[3][0] = ffma2(ad3, bv.x, acc[3][0]); acc[3][1] = ffma2(ad3, bv.y, acc[3][1]);
        }
        __syncthreads();
    }

#pragma unroll
    for (int i = 0; i < 4; i++) {
        int mi = ty * 4 + i;
        if (m0 + mi < cnt) {
            int slot = rows[mi];
            float wt = g_wt[slot];
            float4 ov;
            ov.x = lo2(acc[i][0]) * wt;
            ov.y = hi2(acc[i][0]) * wt;
            ov.z = lo2(acc[i][1]) * wt;
            ov.w = hi2(acc[i][1]) * wt;
            *reinterpret_cast<float4*>(&g_pout[(size_t)slot * DIMD + n0 + tx * 4]) = ov;
        }
    }
}

// Combine: out[t,:] = pout[2t,:] + pout[2t+1,:]  (exact, order-free)
__global__ void combine_kernel(float* __restrict__ out) {
    size_t i = (size_t)blockIdx.x * blockDim.x + threadIdx.x;  // float4 index
    const size_t Q = DIMD / 4;                                 // 256 float4 per row
    if (i < (size_t)NTOK * Q) {
        size_t t = i / Q, q = i % Q;
        const float4* p = reinterpret_cast<const float4*>(g_pout);
        float4 a = p[(2 * t) * Q + q];
        float4 b = p[(2 * t + 1) * Q + q];
        float4 o;
        o.x = a.x + b.x; o.y = a.y + b.y; o.z = a.z + b.z; o.w = a.w + b.w;
        reinterpret_cast<float4*>(out)[i] = o;
    }
}

// ---------------- launcher ----------------
extern "C" void kernel_launch(void* const* d_in, const int* in_sizes, int n_in,
                              void* d_out, int out_size) {
    const float* x  = (const float*)d_in[0];
    const float* gw = (const float*)d_in[1];
    const float* w1 = (const float*)d_in[2];
    const float* w3 = (const float*)d_in[3];
    const float* w2 = (const float*)d_in[4];
    float* out = (float*)d_out;

    init_kernel<<<1, 32>>>();
    router_kernel<<<NTOK / 8, 256>>>(x, gw);                        // 8 warps/block
    ffn1_kernel<<<dim3(HID / TN, NTOK / TM, NEXP), 256>>>(x, w1, w3);
    ffn2_kernel<<<dim3(DIMD / TN, NTOK / TM, NEXP), 256>>>(w2);
    combine_kernel<<<(NTOK * (DIMD / 4) + 255) / 256, 256>>>(out);
}

// round 7
// speedup vs baseline: 2.7742x; 2.7742x over previous
#include <cuda_runtime.h>
#include <cuda_bf16.h>
#include <cstdint>
#include <math.h>

// ---------------- problem constants ----------------
#define NTOK 8192      // B*T
#define DIMD 1024
#define NEXP 8
#define HID  2816
#define NPAIR (2*NTOK)
#define WN   ((size_t)NEXP*HID*DIMD)

// ---------------- device scratch (static; allocations forbidden) ----------------
__device__ __nv_bfloat16 g_w1h[WN], g_w1l[WN];
__device__ __nv_bfloat16 g_w3h[WN], g_w3l[WN];
__device__ __nv_bfloat16 g_w2h[WN], g_w2l[WN];
__device__ __nv_bfloat16 g_xh[(size_t)NTOK*DIMD], g_xl[(size_t)NTOK*DIMD];
__device__ __nv_bfloat16 g_hh[(size_t)NPAIR*HID], g_hl[(size_t)NPAIR*HID];
__device__ float g_pout[(size_t)NPAIR*DIMD];
__device__ int   g_list[NEXP*NTOK];
__device__ float g_wt[NPAIR];
__device__ int   g_cnt[NEXP];

// ---------------- PTX helpers (base PTX only: sm_80+ features) ----------------
static __device__ __forceinline__ uint32_t smem_u32(const void* p) {
    uint32_t a;
    asm("{ .reg .u64 t; cvta.to.shared.u64 t, %1; cvt.u32.u64 %0, t; }" : "=r"(a) : "l"(p));
    return a;
}
static __device__ __forceinline__ void cpa(uint32_t dst, const void* src) {
    asm volatile("cp.async.cg.shared.global [%0], [%1], 16;" :: "r"(dst), "l"(src) : "memory");
}
#define CPA_COMMIT() asm volatile("cp.async.commit_group;" ::: "memory")
#define CPA_WAIT1()  asm volatile("cp.async.wait_group 1;" ::: "memory")
#define CPA_WAIT0()  asm volatile("cp.async.wait_group 0;" ::: "memory")

static __device__ __forceinline__ void ldm_x4(uint32_t a, uint32_t* r) {
    asm volatile("ldmatrix.sync.aligned.m8n8.x4.shared.b16 {%0,%1,%2,%3}, [%4];"
        : "=r"(r[0]), "=r"(r[1]), "=r"(r[2]), "=r"(r[3]) : "r"(a));
}
static __device__ __forceinline__ void ldm_x2(uint32_t a, uint32_t* r) {
    asm volatile("ldmatrix.sync.aligned.m8n8.x2.shared.b16 {%0,%1}, [%2];"
        : "=r"(r[0]), "=r"(r[1]) : "r"(a));
}
static __device__ __forceinline__ void mma16816(float* c, const uint32_t* a, const uint32_t* b) {
    asm volatile("mma.sync.aligned.m16n8k16.row.col.f32.bf16.bf16.f32 "
        "{%0,%1,%2,%3}, {%4,%5,%6,%7}, {%8,%9}, {%0,%1,%2,%3};"
        : "+f"(c[0]), "+f"(c[1]), "+f"(c[2]), "+f"(c[3])
        : "r"(a[0]), "r"(a[1]), "r"(a[2]), "r"(a[3]), "r"(b[0]), "r"(b[1]));
}
static __device__ __forceinline__ uint32_t pack2(__nv_bfloat16 a, __nv_bfloat16 b) {
    return (uint32_t)__bfloat16_as_ushort(a) | ((uint32_t)__bfloat16_as_ushort(b) << 16);
}

// smem row stride: 72 bf16 = 144B. Rows rotate 16B mod 128B -> ldmatrix conflict-free.
#define RS 144

// ---------------- small kernels ----------------
__global__ void init_kernel() {
    if (threadIdx.x < NEXP) g_cnt[threadIdx.x] = 0;
}

__global__ void cvt_kernel(const float* __restrict__ src,
                           __nv_bfloat16* __restrict__ hi,
                           __nv_bfloat16* __restrict__ lo, int n4) {
    int i = blockIdx.x * blockDim.x + threadIdx.x;
    if (i >= n4) return;
    float4 v = reinterpret_cast<const float4*>(src)[i];
    __nv_bfloat16 h0 = __float2bfloat16(v.x), h1 = __float2bfloat16(v.y);
    __nv_bfloat16 h2 = __float2bfloat16(v.z), h3 = __float2bfloat16(v.w);
    __nv_bfloat16 l0 = __float2bfloat16(v.x - __bfloat162float(h0));
    __nv_bfloat16 l1 = __float2bfloat16(v.y - __bfloat162float(h1));
    __nv_bfloat16 l2 = __float2bfloat16(v.z - __bfloat162float(h2));
    __nv_bfloat16 l3 = __float2bfloat16(v.w - __bfloat162float(h3));
    uint2 H; H.x = pack2(h0, h1); H.y = pack2(h2, h3);
    uint2 L; L.x = pack2(l0, l1); L.y = pack2(l2, l3);
    reinterpret_cast<uint2*>(hi)[i] = H;
    reinterpret_cast<uint2*>(lo)[i] = L;
}

__global__ void router_kernel(const float* __restrict__ x,
                              const float* __restrict__ gw) {
    int w    = (blockIdx.x * blockDim.x + threadIdx.x) >> 5;
    int lane = threadIdx.x & 31;
    if (w >= NTOK) return;
    const float* xr = x + (size_t)w * DIMD;
    float acc[NEXP];
#pragma unroll
    for (int e = 0; e < NEXP; e++) acc[e] = 0.f;
    for (int d = lane; d < DIMD; d += 32) {
        float xv = xr[d];
#pragma unroll
        for (int e = 0; e < NEXP; e++) acc[e] += xv * gw[e * DIMD + d];
    }
#pragma unroll
    for (int e = 0; e < NEXP; e++)
#pragma unroll
        for (int o = 16; o > 0; o >>= 1)
            acc[e] += __shfl_xor_sync(0xffffffffu, acc[e], o);
    if (lane == 0) {
        float m = acc[0];
#pragma unroll
        for (int e = 1; e < NEXP; e++) m = fmaxf(m, acc[e]);
        float p[NEXP];
#pragma unroll
        for (int e = 0; e < NEXP; e++) p[e] = __expf(acc[e] - m);
        int i0 = 0; float b0 = p[0];
#pragma unroll
        for (int e = 1; e < NEXP; e++) if (p[e] > b0) { b0 = p[e]; i0 = e; }
        int i1 = -1; float b1 = -1.f;
#pragma unroll
        for (int e = 0; e < NEXP; e++) if (e != i0 && p[e] > b1) { b1 = p[e]; i1 = e; }
        float s = b0 + b1;
        g_wt[2 * w]     = b0 / s;
        g_wt[2 * w + 1] = b1 / s;
        int pos0 = atomicAdd(&g_cnt[i0], 1);
        g_list[i0 * NTOK + pos0] = 2 * w;
        int pos1 = atomicAdd(&g_cnt[i1], 1);
        g_list[i1 * NTOK + pos1] = 2 * w + 1;
    }
}

// =======================================================================
// Stage A: CTA tile M=128 x N=64 (per matrix, w1 & w3), K chunks of 64.
// 8 warps: 2 (M) x 4 (N). Warp tile: 64M x 16N per matrix.
// Per-buffer smem: Ah 18432 | Al 18432 | B1h 9216 | B1l 9216 | B3h 9216 | B3l 9216
// =======================================================================
extern __shared__ char dynsmem[];

#define F1_BUFSZ 73728
#define F1_AH 0
#define F1_AL 18432
#define F1_B1H 36864
#define F1_B1L 46080
#define F1_B3H 55296
#define F1_B3L 64512

__global__ __launch_bounds__(256) void ffn1_mma() {
    int e   = blockIdx.z;
    int cnt = g_cnt[e];
    int m0  = blockIdx.y * 128;
    if (m0 >= cnt) return;
    int n0  = blockIdx.x * 64;

    int* s_rows = reinterpret_cast<int*>(dynsmem);
    uint32_t sb = smem_u32(dynsmem) + 1024;  // buffers start

    int tid = threadIdx.x, lane = tid & 31, wid = tid >> 5;
    if (tid < 128) s_rows[tid] = g_list[e * NTOK + min(m0 + tid, cnt - 1)];
    __syncthreads();

    const __nv_bfloat16* W1h = g_w1h + (size_t)e * HID * DIMD;
    const __nv_bfloat16* W1l = g_w1l + (size_t)e * HID * DIMD;
    const __nv_bfloat16* W3h = g_w3h + (size_t)e * HID * DIMD;
    const __nv_bfloat16* W3l = g_w3l + (size_t)e * HID * DIMD;

    float acc1[4][2][4], acc3[4][2][4];
#pragma unroll
    for (int mt = 0; mt < 4; mt++)
#pragma unroll
        for (int nt = 0; nt < 2; nt++)
#pragma unroll
            for (int q = 0; q < 4; q++) { acc1[mt][nt][q] = 0.f; acc3[mt][nt][q] = 0.f; }

    int wm = (wid >> 2) * 64;   // warp M offset
    int wn = (wid & 3) * 16;    // warp N offset (per matrix)

    // chunk loader
    auto load_chunk = [&](uint32_t bb, int k0) {
#pragma unroll
        for (int it = 0; it < 4; it++) {
            int i = tid + it * 256;           // 1024 iters: A
            int r = i >> 3, c = i & 7;
            int tok = s_rows[r] >> 1;
            size_t off = (size_t)tok * DIMD + k0 + c * 8;
            cpa(bb + F1_AH + r * RS + c * 16, g_xh + off);
            cpa(bb + F1_AL + r * RS + c * 16, g_xl + off);
        }
#pragma unroll
        for (int it = 0; it < 2; it++) {
            int i = tid + it * 256;           // 512 iters: B
            int r = i >> 3, c = i & 7;
            size_t off = (size_t)(n0 + r) * DIMD + k0 + c * 8;
            cpa(bb + F1_B1H + r * RS + c * 16, W1h + off);
            cpa(bb + F1_B1L + r * RS + c * 16, W1l + off);
            cpa(bb + F1_B3H + r * RS + c * 16, W3h + off);
            cpa(bb + F1_B3L + r * RS + c * 16, W3l + off);
        }
        CPA_COMMIT();
    };

    load_chunk(sb, 0);

    for (int kc = 0; kc < DIMD / 64; kc++) {
        uint32_t bb = sb + (kc & 1) * F1_BUFSZ;
        if (kc + 1 < DIMD / 64) {
            load_chunk(sb + ((kc + 1) & 1) * F1_BUFSZ, (kc + 1) * 64);
            CPA_WAIT1();
        } else {
            CPA_WAIT0();
        }
        __syncthreads();

#pragma unroll
        for (int ks = 0; ks < 4; ks++) {
            uint32_t ah[4][4], al[4][4];
            int arow = wm + (lane & 15);
            int acol = ks * 16 + ((lane >> 4) << 3);
#pragma unroll
            for (int mt = 0; mt < 4; mt++) {
                uint32_t ao = (uint32_t)((arow + mt * 16) * RS + acol * 2);
                ldm_x4(bb + F1_AH + ao, ah[mt]);
                ldm_x4(bb + F1_AL + ao, al[mt]);
            }
            int l8 = lane & 15;
            int brow = wn + (l8 & 7);
            int bcol = ks * 16 + ((l8 >> 3) << 3);
#pragma unroll
            for (int nt = 0; nt < 2; nt++) {
                uint32_t bo = (uint32_t)((brow + nt * 8) * RS + bcol * 2);
                uint32_t b1h[2], b1l[2], b3h[2], b3l[2];
                ldm_x2(bb + F1_B1H + bo, b1h);
                ldm_x2(bb + F1_B1L + bo, b1l);
                ldm_x2(bb + F1_B3H + bo, b3h);
                ldm_x2(bb + F1_B3L + bo, b3l);
#pragma unroll
                for (int mt = 0; mt < 4; mt++) {
                    mma16816(acc1[mt][nt], ah[mt], b1h);
                    mma16816(acc1[mt][nt], ah[mt], b1l);
                    mma16816(acc1[mt][nt], al[mt], b1h);
                    mma16816(acc3[mt][nt], ah[mt], b3h);
                    mma16816(acc3[mt][nt], ah[mt], b3l);
                    mma16816(acc3[mt][nt], al[mt], b3h);
                }
            }
        }
        __syncthreads();
    }

    // epilogue: h = silu(acc1) * acc3, split hi/lo, store to g_hh/g_hl
    uint32_t* HH = reinterpret_cast<uint32_t*>(g_hh);
    uint32_t* HL = reinterpret_cast<uint32_t*>(g_hl);
#pragma unroll
    for (int mt = 0; mt < 4; mt++) {
#pragma unroll
        for (int nt = 0; nt < 2; nt++) {
#pragma unroll
            for (int half = 0; half < 2; half++) {
                int mi = wm + mt * 16 + (lane >> 2) + half * 8;
                if (m0 + mi >= cnt) continue;
                int slot = s_rows[mi];
                int gn = n0 + wn + nt * 8 + 2 * (lane & 3);
                float a = acc1[mt][nt][half * 2];
                float b = acc1[mt][nt][half * 2 + 1];
                float g = acc3[mt][nt][half * 2];
                float h = acc3[mt][nt][half * 2 + 1];
                float h0 = a / (1.f + __expf(-a)) * g;
                float h1 = b / (1.f + __expf(-b)) * h;
                __nv_bfloat16 H0 = __float2bfloat16(h0), H1 = __float2bfloat16(h1);
                __nv_bfloat16 L0 = __float2bfloat16(h0 - __bfloat162float(H0));
                __nv_bfloat16 L1 = __float2bfloat16(h1 - __bfloat162float(H1));
                size_t idx = ((size_t)slot * HID + gn) >> 1;
                HH[idx] = pack2(H0, H1);
                HL[idx] = pack2(L0, L1);
            }
        }
    }
}

// =======================================================================
// Stage B: CTA tile M=128 x N=128 over DIMD, K=HID chunks of 64.
// 8 warps: 2 (M) x 4 (N). Warp tile 64M x 32N.
// Per-buffer smem: Ah 18432 | Al 18432 | Bh 18432 | Bl 18432
// =======================================================================
#define F2_BUFSZ 73728
#define F2_AH 0
#define F2_AL 18432
#define F2_BH 36864
#define F2_BL 55296

__global__ __launch_bounds__(256) void ffn2_mma() {
    int e   = blockIdx.z;
    int cnt = g_cnt[e];
    int m0  = blockIdx.y * 128;
    if (m0 >= cnt) return;
    int n0  = blockIdx.x * 128;

    int* s_rows = reinterpret_cast<int*>(dynsmem);
    uint32_t sb = smem_u32(dynsmem) + 1024;

    int tid = threadIdx.x, lane = tid & 31, wid = tid >> 5;
    if (tid < 128) s_rows[tid] = g_list[e * NTOK + min(m0 + tid, cnt - 1)];
    __syncthreads();

    const __nv_bfloat16* W2h = g_w2h + (size_t)e * DIMD * HID;
    const __nv_bfloat16* W2l = g_w2l + (size_t)e * DIMD * HID;

    float acc[4][4][4];
#pragma unroll
    for (int mt = 0; mt < 4; mt++)
#pragma unroll
        for (int nt = 0; nt < 4; nt++)
#pragma unroll
            for (int q = 0; q < 4; q++) acc[mt][nt][q] = 0.f;

    int wm = (wid >> 2) * 64;
    int wn = (wid & 3) * 32;

    auto load_chunk = [&](uint32_t bb, int k0) {
#pragma unroll
        for (int it = 0; it < 4; it++) {
            int i = tid + it * 256;           // 1024: A rows
            int r = i >> 3, c = i & 7;
            int slot = s_rows[r];
            size_t off = (size_t)slot * HID + k0 + c * 8;
            cpa(bb + F2_AH + r * RS + c * 16, g_hh + off);
            cpa(bb + F2_AL + r * RS + c * 16, g_hl + off);
        }
#pragma unroll
        for (int it = 0; it < 4; it++) {
            int i = tid + it * 256;           // 1024: B rows
            int r = i >> 3, c = i & 7;
            size_t off = (size_t)(n0 + r) * HID + k0 + c * 8;
            cpa(bb + F2_BH + r * RS + c * 16, W2h + off);
            cpa(bb + F2_BL + r * RS + c * 16, W2l + off);
        }
        CPA_COMMIT();
    };

    load_chunk(sb, 0);

    for (int kc = 0; kc < HID / 64; kc++) {
        uint32_t bb = sb + (kc & 1) * F2_BUFSZ;
        if (kc + 1 < HID / 64) {
            load_chunk(sb + ((kc + 1) & 1) * F2_BUFSZ, (kc + 1) * 64);
            CPA_WAIT1();
        } else {
            CPA_WAIT0();
        }
        __syncthreads();

#pragma unroll
        for (int ks = 0; ks < 4; ks++) {
            uint32_t ah[4][4], al[4][4];
            int arow = wm + (lane & 15);
            int acol = ks * 16 + ((lane >> 4) << 3);
#pragma unroll
            for (int mt = 0; mt < 4; mt++) {
                uint32_t ao = (uint32_t)((arow + mt * 16) * RS + acol * 2);
                ldm_x4(bb + F2_AH + ao, ah[mt]);
                ldm_x4(bb + F2_AL + ao, al[mt]);
            }
            int l8 = lane & 15;
            int brow = wn + (l8 & 7);
            int bcol = ks * 16 + ((l8 >> 3) << 3);
#pragma unroll
            for (int nt = 0; nt < 4; nt++) {
                uint32_t bo = (uint32_t)((brow + nt * 8) * RS + bcol * 2);
                uint32_t bh[2], bl[2];
                ldm_x2(bb + F2_BH + bo, bh);
                ldm_x2(bb + F2_BL + bo, bl);
#pragma unroll
                for (int mt = 0; mt < 4; mt++) {
                    mma16816(acc[mt][nt], ah[mt], bh);
                    mma16816(acc[mt][nt], ah[mt], bl);
                    mma16816(acc[mt][nt], al[mt], bh);
                }
            }
        }
        __syncthreads();
    }

    // epilogue: pout = acc * wt[slot]
#pragma unroll
    for (int mt = 0; mt < 4; mt++) {
#pragma unroll
        for (int half = 0; half < 2; half++) {
            int mi = wm + mt * 16 + (lane >> 2) + half * 8;
            if (m0 + mi >= cnt) continue;
            int slot = s_rows[mi];
            float wt = g_wt[slot];
            float* row = g_pout + (size_t)slot * DIMD;
#pragma unroll
            for (int nt = 0; nt < 4; nt++) {
                int gn = n0 + wn + nt * 8 + 2 * (lane & 3);
                float2 v;
                v.x = acc[mt][nt][half * 2] * wt;
                v.y = acc[mt][nt][half * 2 + 1] * wt;
                *reinterpret_cast<float2*>(row + gn) = v;
            }
        }
    }
}

// ---------------- combine ----------------
__global__ void combine_kernel(float* __restrict__ out) {
    size_t i = (size_t)blockIdx.x * blockDim.x + threadIdx.x;
    const size_t Q = DIMD / 4;
    if (i < (size_t)NTOK * Q) {
        size_t t = i / Q, q = i % Q;
        const float4* p = reinterpret_cast<const float4*>(g_pout);
        float4 a = p[(2 * t) * Q + q];
        float4 b = p[(2 * t + 1) * Q + q];
        float4 o;
        o.x = a.x + b.x; o.y = a.y + b.y; o.z = a.z + b.z; o.w = a.w + b.w;
        reinterpret_cast<float4*>(out)[i] = o;
    }
}

// ---------------- launcher ----------------
extern "C" void kernel_launch(void* const* d_in, const int* in_sizes, int n_in,
                              void* d_out, int out_size) {
    const float* x  = (const float*)d_in[0];
    const float* gw = (const float*)d_in[1];
    const float* w1 = (const float*)d_in[2];
    const float* w3 = (const float*)d_in[3];
    const float* w2 = (const float*)d_in[4];
    float* out = (float*)d_out;

    __nv_bfloat16 *xh, *xl, *w1h, *w1l, *w3h, *w3l, *w2h, *w2l;
    cudaGetSymbolAddress((void**)&xh,  g_xh);  cudaGetSymbolAddress((void**)&xl,  g_xl);
    cudaGetSymbolAddress((void**)&w1h, g_w1h); cudaGetSymbolAddress((void**)&w1l, g_w1l);
    cudaGetSymbolAddress((void**)&w3h, g_w3h); cudaGetSymbolAddress((void**)&w3l, g_w3l);
    cudaGetSymbolAddress((void**)&w2h, g_w2h); cudaGetSymbolAddress((void**)&w2l, g_w2l);

    const int SMEM = 1024 + 2 * F1_BUFSZ;  // 148480 (same for both stages)
    cudaFuncSetAttribute(ffn1_mma, cudaFuncAttributeMaxDynamicSharedMemorySize, SMEM);
    cudaFuncSetAttribute(ffn2_mma, cudaFuncAttributeMaxDynamicSharedMemorySize, SMEM);

    init_kernel<<<1, 32>>>();
    router_kernel<<<NTOK / 8, 256>>>(x, gw);

    int xn4 = NTOK * DIMD / 4;
    int wn4 = (int)(WN / 4);
    cvt_kernel<<<(xn4 + 255) / 256, 256>>>(x,  xh,  xl,  xn4);
    cvt_kernel<<<(wn4 + 255) / 256, 256>>>(w1, w1h, w1l, wn4);
    cvt_kernel<<<(wn4 + 255) / 256, 256>>>(w3, w3h, w3l, wn4);
    cvt_kernel<<<(wn4 + 255) / 256, 256>>>(w2, w2h, w2l, wn4);

    ffn1_mma<<<dim3(HID / 64, NTOK / 128, NEXP), 256, SMEM>>>();
    ffn2_mma<<<dim3(DIMD / 128, NTOK / 128, NEXP), 256, SMEM>>>();
    combine_kernel<<<(NTOK * (DIMD / 4) + 255) / 256, 256>>>(out);
}

// round 8
// speedup vs baseline: 2.9148x; 1.0507x over previous
#include <cuda_runtime.h>
#include <cuda_bf16.h>
#include <cstdint>
#include <math.h>

// ---------------- problem constants ----------------
#define NTOK 8192      // B*T
#define DIMD 1024
#define NEXP 8
#define HID  2816
#define NPAIR (2*NTOK)
#define WN   ((size_t)NEXP*HID*DIMD)

// ---------------- device scratch (static; allocations forbidden) ----------------
__device__ __nv_bfloat16 g_w1h[WN], g_w1l[WN];
__device__ __nv_bfloat16 g_w3h[WN], g_w3l[WN];
__device__ __nv_bfloat16 g_w2h[WN], g_w2l[WN];
__device__ __nv_bfloat16 g_xh[(size_t)NTOK*DIMD], g_xl[(size_t)NTOK*DIMD];
__device__ __nv_bfloat16 g_hh[(size_t)NPAIR*HID], g_hl[(size_t)NPAIR*HID];
__device__ float g_pout[(size_t)NPAIR*DIMD];
__device__ int   g_list[NEXP*NTOK];
__device__ float g_wt[NPAIR];
__device__ int   g_cnt[NEXP];

// ---------------- PTX helpers (base PTX only: sm_80+ features) ----------------
static __device__ __forceinline__ uint32_t smem_u32(const void* p) {
    uint32_t a;
    asm("{ .reg .u64 t; cvta.to.shared.u64 t, %1; cvt.u32.u64 %0, t; }" : "=r"(a) : "l"(p));
    return a;
}
static __device__ __forceinline__ void cpa(uint32_t dst, const void* src) {
    asm volatile("cp.async.cg.shared.global [%0], [%1], 16;" :: "r"(dst), "l"(src) : "memory");
}
#define CPA_COMMIT() asm volatile("cp.async.commit_group;" ::: "memory")
#define CPA_WAIT1()  asm volatile("cp.async.wait_group 1;" ::: "memory")
#define CPA_WAIT0()  asm volatile("cp.async.wait_group 0;" ::: "memory")

static __device__ __forceinline__ void ldm_x4(uint32_t a, uint32_t* r) {
    asm volatile("ldmatrix.sync.aligned.m8n8.x4.shared.b16 {%0,%1,%2,%3}, [%4];"
        : "=r"(r[0]), "=r"(r[1]), "=r"(r[2]), "=r"(r[3]) : "r"(a));
}
static __device__ __forceinline__ void mma16816(float* c, const uint32_t* a, const uint32_t* b) {
    asm volatile("mma.sync.aligned.m16n8k16.row.col.f32.bf16.bf16.f32 "
        "{%0,%1,%2,%3}, {%4,%5,%6,%7}, {%8,%9}, {%0,%1,%2,%3};"
        : "+f"(c[0]), "+f"(c[1]), "+f"(c[2]), "+f"(c[3])
        : "r"(a[0]), "r"(a[1]), "r"(a[2]), "r"(a[3]), "r"(b[0]), "r"(b[1]));
}
static __device__ __forceinline__ uint32_t pack2(__nv_bfloat16 a, __nv_bfloat16 b) {
    return (uint32_t)__bfloat16_as_ushort(a) | ((uint32_t)__bfloat16_as_ushort(b) << 16);
}

// smem row stride: 72 bf16 = 144B. Rows rotate 16B mod 128B -> ldmatrix conflict-free.
#define RS 144

// Unified GEMM geometry (both stages): CTA M=128 x N=256 (B-tile rows),
// 8 warps as 2(M) x 4(N): warp tile 64M x 64N (mt=4, nt=8). K-chunk 64, 2-buf.
#define OFF_AH 0
#define OFF_AL 18432
#define OFF_BH 36864
#define OFF_BL 73728
#define BUFSZ  110592
#define SMEM_TOTAL (1024 + 2*BUFSZ)   // 222208

// ---------------- small kernels ----------------
__global__ void init_kernel() {
    if (threadIdx.x < NEXP) g_cnt[threadIdx.x] = 0;
}

__global__ void cvt_kernel(const float* __restrict__ src,
                           __nv_bfloat16* __restrict__ hi,
                           __nv_bfloat16* __restrict__ lo, int n4) {
    int i = blockIdx.x * blockDim.x + threadIdx.x;
    if (i >= n4) return;
    float4 v = reinterpret_cast<const float4*>(src)[i];
    __nv_bfloat16 h0 = __float2bfloat16(v.x), h1 = __float2bfloat16(v.y);
    __nv_bfloat16 h2 = __float2bfloat16(v.z), h3 = __float2bfloat16(v.w);
    __nv_bfloat16 l0 = __float2bfloat16(v.x - __bfloat162float(h0));
    __nv_bfloat16 l1 = __float2bfloat16(v.y - __bfloat162float(h1));
    __nv_bfloat16 l2 = __float2bfloat16(v.z - __bfloat162float(h2));
    __nv_bfloat16 l3 = __float2bfloat16(v.w - __bfloat162float(h3));
    uint2 H; H.x = pack2(h0, h1); H.y = pack2(h2, h3);
    uint2 L; L.x = pack2(l0, l1); L.y = pack2(l2, l3);
    reinterpret_cast<uint2*>(hi)[i] = H;
    reinterpret_cast<uint2*>(lo)[i] = L;
}

__global__ void router_kernel(const float* __restrict__ x,
                              const float* __restrict__ gw) {
    int w    = (blockIdx.x * blockDim.x + threadIdx.x) >> 5;
    int lane = threadIdx.x & 31;
    if (w >= NTOK) return;
    const float* xr = x + (size_t)w * DIMD;
    float acc[NEXP];
#pragma unroll
    for (int e = 0; e < NEXP; e++) acc[e] = 0.f;
    for (int d = lane; d < DIMD; d += 32) {
        float xv = xr[d];
#pragma unroll
        for (int e = 0; e < NEXP; e++) acc[e] += xv * gw[e * DIMD + d];
    }
#pragma unroll
    for (int e = 0; e < NEXP; e++)
#pragma unroll
        for (int o = 16; o > 0; o >>= 1)
            acc[e] += __shfl_xor_sync(0xffffffffu, acc[e], o);
    if (lane == 0) {
        float m = acc[0];
#pragma unroll
        for (int e = 1; e < NEXP; e++) m = fmaxf(m, acc[e]);
        float p[NEXP];
#pragma unroll
        for (int e = 0; e < NEXP; e++) p[e] = __expf(acc[e] - m);
        int i0 = 0; float b0 = p[0];
#pragma unroll
        for (int e = 1; e < NEXP; e++) if (p[e] > b0) { b0 = p[e]; i0 = e; }
        int i1 = -1; float b1 = -1.f;
#pragma unroll
        for (int e = 0; e < NEXP; e++) if (e != i0 && p[e] > b1) { b1 = p[e]; i1 = e; }
        float s = b0 + b1;
        g_wt[2 * w]     = b0 / s;
        g_wt[2 * w + 1] = b1 / s;
        int pos0 = atomicAdd(&g_cnt[i0], 1);
        g_list[i0 * NTOK + pos0] = 2 * w;
        int pos1 = atomicAdd(&g_cnt[i1], 1);
        g_list[i1 * NTOK + pos1] = 2 * w + 1;
    }
}

extern __shared__ char dynsmem[];

// =======================================================================
// Stage A: single GEMM with w1/w3 rows interleaved in the B tile:
//   B-tile row 2j   = w1[hidden n0h+j]
//   B-tile row 2j+1 = w3[hidden n0h+j]
// Output cols pair even/odd = (w1-dot, w3-dot) of the SAME hidden index,
// landing in the same thread's (c0,c1)/(c2,c3) register pairs -> SwiGLU is
// thread-local. CTA covers 128 hidden indices (256 B rows); grid x = HID/128.
// =======================================================================
__global__ __launch_bounds__(256, 1) void ffn1_mma() {
    int e   = blockIdx.z;
    int cnt = g_cnt[e];
    int m0  = blockIdx.y * 128;
    if (m0 >= cnt) return;
    int n0h = blockIdx.x * 128;   // hidden base

    int* s_rows = reinterpret_cast<int*>(dynsmem);
    uint32_t sb = smem_u32(dynsmem) + 1024;

    int tid = threadIdx.x, lane = tid & 31, wid = tid >> 5;
    if (tid < 128) s_rows[tid] = g_list[e * NTOK + min(m0 + tid, cnt - 1)];
    __syncthreads();

    const __nv_bfloat16* W1h = g_w1h + (size_t)e * HID * DIMD;
    const __nv_bfloat16* W1l = g_w1l + (size_t)e * HID * DIMD;
    const __nv_bfloat16* W3h = g_w3h + (size_t)e * HID * DIMD;
    const __nv_bfloat16* W3l = g_w3l + (size_t)e * HID * DIMD;

    float acc[4][8][4];
#pragma unroll
    for (int mt = 0; mt < 4; mt++)
#pragma unroll
        for (int nt = 0; nt < 8; nt++)
#pragma unroll
            for (int q = 0; q < 4; q++) acc[mt][nt][q] = 0.f;

    int wm = (wid >> 2) * 64;
    int wn = (wid & 3) * 64;     // B-tile col offset (= 32 hidden)

    auto load_chunk = [&](uint32_t bb, int k0) {
#pragma unroll
        for (int it = 0; it < 4; it++) {         // A: 128 rows
            int i = tid + it * 256;
            int r = i >> 3, c = i & 7;
            int tok = s_rows[r] >> 1;
            size_t off = (size_t)tok * DIMD + k0 + c * 8;
            cpa(bb + OFF_AH + r * RS + c * 16, g_xh + off);
            cpa(bb + OFF_AL + r * RS + c * 16, g_xl + off);
        }
#pragma unroll
        for (int it = 0; it < 8; it++) {         // B: 256 interleaved rows
            int i = tid + it * 256;
            int r = i >> 3, c = i & 7;
            int j = n0h + (r >> 1);
            const __nv_bfloat16* sh = (r & 1) ? W3h : W1h;
            const __nv_bfloat16* sl = (r & 1) ? W3l : W1l;
            size_t off = (size_t)j * DIMD + k0 + c * 8;
            cpa(bb + OFF_BH + r * RS + c * 16, sh + off);
            cpa(bb + OFF_BL + r * RS + c * 16, sl + off);
        }
        CPA_COMMIT();
    };

    load_chunk(sb, 0);

    for (int kc = 0; kc < DIMD / 64; kc++) {
        uint32_t bb = sb + (kc & 1) * BUFSZ;
        if (kc + 1 < DIMD / 64) {
            load_chunk(sb + ((kc + 1) & 1) * BUFSZ, (kc + 1) * 64);
            CPA_WAIT1();
        } else {
            CPA_WAIT0();
        }
        __syncthreads();

#pragma unroll
        for (int ks = 0; ks < 4; ks++) {
            uint32_t ah[4][4], al[4][4];
            int arow = wm + (lane & 15);
            int acol = ks * 16 + ((lane >> 4) << 3);
#pragma unroll
            for (int mt = 0; mt < 4; mt++) {
                uint32_t ao = (uint32_t)((arow + mt * 16) * RS + acol * 2);
                ldm_x4(bb + OFF_AH + ao, ah[mt]);
                ldm_x4(bb + OFF_AL + ao, al[mt]);
            }
            int brow = wn + (lane & 7) + ((lane >> 4) << 3);
            int bcol = ks * 16 + ((lane >> 3) & 1) * 8;
#pragma unroll
            for (int ntp = 0; ntp < 4; ntp++) {
                uint32_t bo = (uint32_t)((brow + ntp * 16) * RS + bcol * 2);
                uint32_t bh4[4], bl4[4];
                ldm_x4(bb + OFF_BH + bo, bh4);
                ldm_x4(bb + OFF_BL + bo, bl4);
#pragma unroll
                for (int mt = 0; mt < 4; mt++) {
                    mma16816(acc[mt][2*ntp],   ah[mt], bh4);
                    mma16816(acc[mt][2*ntp],   ah[mt], bl4);
                    mma16816(acc[mt][2*ntp],   al[mt], bh4);
                    mma16816(acc[mt][2*ntp+1], ah[mt], bh4 + 2);
                    mma16816(acc[mt][2*ntp+1], ah[mt], bl4 + 2);
                    mma16816(acc[mt][2*ntp+1], al[mt], bh4 + 2);
                }
            }
        }
        __syncthreads();
    }

    // epilogue: c0=w1-dot (even col), c1=w3-dot (odd col), same hidden index.
    // pair even/odd hidden via shfl_xor(1) so even lanes issue 4B stores.
    uint32_t* HH = reinterpret_cast<uint32_t*>(g_hh);
    uint32_t* HL = reinterpret_cast<uint32_t*>(g_hl);
    int hb = n0h + (wn >> 1) + (lane & 3);   // + nt*4 below
#pragma unroll
    for (int mt = 0; mt < 4; mt++) {
#pragma unroll
        for (int half = 0; half < 2; half++) {
            int mi = wm + mt * 16 + (lane >> 2) + half * 8;
            bool valid = (m0 + mi) < cnt;
            int slot = s_rows[mi];
#pragma unroll
            for (int nt = 0; nt < 8; nt++) {
                float c0 = acc[mt][nt][half * 2];
                float c1 = acc[mt][nt][half * 2 + 1];
                float h = c0 / (1.f + __expf(-c0)) * c1;
                __nv_bfloat16 Hh = __float2bfloat16(h);
                __nv_bfloat16 Lh = __float2bfloat16(h - __bfloat162float(Hh));
                uint32_t hl = pack2(Hh, Lh);
                uint32_t other = __shfl_xor_sync(0xffffffffu, hl, 1);
                if (!(lane & 1) && valid) {
                    int hidden = hb + nt * 4;            // even
                    size_t idx = ((size_t)slot * HID + hidden) >> 1;
                    HH[idx] = (hl & 0xffffu) | ((other & 0xffffu) << 16);
                    HL[idx] = (hl >> 16) | (other & 0xffff0000u);
                }
            }
        }
    }
}

// =======================================================================
// Stage B: pout = (h @ w2^T) * wt.  CTA M=128 x N=256 over DIMD (grid x=4),
// K=HID in chunks of 64. Same warp geometry as stage A.
// =======================================================================
__global__ __launch_bounds__(256, 1) void ffn2_mma() {
    int e   = blockIdx.z;
    int cnt = g_cnt[e];
    int m0  = blockIdx.y * 128;
    if (m0 >= cnt) return;
    int n0  = blockIdx.x * 256;

    int* s_rows = reinterpret_cast<int*>(dynsmem);
    uint32_t sb = smem_u32(dynsmem) + 1024;

    int tid = threadIdx.x, lane = tid & 31, wid = tid >> 5;
    if (tid < 128) s_rows[tid] = g_list[e * NTOK + min(m0 + tid, cnt - 1)];
    __syncthreads();

    const __nv_bfloat16* W2h = g_w2h + (size_t)e * DIMD * HID;
    const __nv_bfloat16* W2l = g_w2l + (size_t)e * DIMD * HID;

    float acc[4][8][4];
#pragma unroll
    for (int mt = 0; mt < 4; mt++)
#pragma unroll
        for (int nt = 0; nt < 8; nt++)
#pragma unroll
            for (int q = 0; q < 4; q++) acc[mt][nt][q] = 0.f;

    int wm = (wid >> 2) * 64;
    int wn = (wid & 3) * 64;

    auto load_chunk = [&](uint32_t bb, int k0) {
#pragma unroll
        for (int it = 0; it < 4; it++) {         // A: 128 rows (gathered h)
            int i = tid + it * 256;
            int r = i >> 3, c = i & 7;
            int slot = s_rows[r];
            size_t off = (size_t)slot * HID + k0 + c * 8;
            cpa(bb + OFF_AH + r * RS + c * 16, g_hh + off);
            cpa(bb + OFF_AL + r * RS + c * 16, g_hl + off);
        }
#pragma unroll
        for (int it = 0; it < 8; it++) {         // B: 256 w2 rows
            int i = tid + it * 256;
            int r = i >> 3, c = i & 7;
            size_t off = (size_t)(n0 + r) * HID + k0 + c * 8;
            cpa(bb + OFF_BH + r * RS + c * 16, W2h + off);
            cpa(bb + OFF_BL + r * RS + c * 16, W2l + off);
        }
        CPA_COMMIT();
    };

    load_chunk(sb, 0);

    for (int kc = 0; kc < HID / 64; kc++) {
        uint32_t bb = sb + (kc & 1) * BUFSZ;
        if (kc + 1 < HID / 64) {
            load_chunk(sb + ((kc + 1) & 1) * BUFSZ, (kc + 1) * 64);
            CPA_WAIT1();
        } else {
            CPA_WAIT0();
        }
        __syncthreads();

#pragma unroll
        for (int ks = 0; ks < 4; ks++) {
            uint32_t ah[4][4], al[4][4];
            int arow = wm + (lane & 15);
            int acol = ks * 16 + ((lane >> 4) << 3);
#pragma unroll
            for (int mt = 0; mt < 4; mt++) {
                uint32_t ao = (uint32_t)((arow + mt * 16) * RS + acol * 2);
                ldm_x4(bb + OFF_AH + ao, ah[mt]);
                ldm_x4(bb + OFF_AL + ao, al[mt]);
            }
            int brow = wn + (lane & 7) + ((lane >> 4) << 3);
            int bcol = ks * 16 + ((lane >> 3) & 1) * 8;
#pragma unroll
            for (int ntp = 0; ntp < 4; ntp++) {
                uint32_t bo = (uint32_t)((brow + ntp * 16) * RS + bcol * 2);
                uint32_t bh4[4], bl4[4];
                ldm_x4(bb + OFF_BH + bo, bh4);
                ldm_x4(bb + OFF_BL + bo, bl4);
#pragma unroll
                for (int mt = 0; mt < 4; mt++) {
                    mma16816(acc[mt][2*ntp],   ah[mt], bh4);
                    mma16816(acc[mt][2*ntp],   ah[mt], bl4);
                    mma16816(acc[mt][2*ntp],   al[mt], bh4);
                    mma16816(acc[mt][2*ntp+1], ah[mt], bh4 + 2);
                    mma16816(acc[mt][2*ntp+1], ah[mt], bl4 + 2);
                    mma16816(acc[mt][2*ntp+1], al[mt], bh4 + 2);
                }
            }
        }
        __syncthreads();
    }

    // epilogue: pout = acc * wt[slot]
#pragma unroll
    for (int mt = 0; mt < 4; mt++) {
#pragma unroll
        for (int half = 0; half < 2; half++) {
            int mi = wm + mt * 16 + (lane >> 2) + half * 8;
            if (m0 + mi >= cnt) continue;
            int slot = s_rows[mi];
            float wt = g_wt[slot];
            float* row = g_pout + (size_t)slot * DIMD;
#pragma unroll
            for (int nt = 0; nt < 8; nt++) {
                int gn = n0 + wn + nt * 8 + 2 * (lane & 3);
                float2 v;
                v.x = acc[mt][nt][half * 2] * wt;
                v.y = acc[mt][nt][half * 2 + 1] * wt;
                *reinterpret_cast<float2*>(row + gn) = v;
            }
        }
    }
}

// ---------------- combine ----------------
__global__ void combine_kernel(float* __restrict__ out) {
    size_t i = (size_t)blockIdx.x * blockDim.x + threadIdx.x;
    const size_t Q = DIMD / 4;
    if (i < (size_t)NTOK * Q) {
        size_t t = i / Q, q = i % Q;
        const float4* p = reinterpret_cast<const float4*>(g_pout);
        float4 a = p[(2 * t) * Q + q];
        float4 b = p[(2 * t + 1) * Q + q];
        float4 o;
        o.x = a.x + b.x; o.y = a.y + b.y; o.z = a.z + b.z; o.w = a.w + b.w;
        reinterpret_cast<float4*>(out)[i] = o;
    }
}

// ---------------- launcher ----------------
extern "C" void kernel_launch(void* const* d_in, const int* in_sizes, int n_in,
                              void* d_out, int out_size) {
    const float* x  = (const float*)d_in[0];
    const float* gw = (const float*)d_in[1];
    const float* w1 = (const float*)d_in[2];
    const float* w3 = (const float*)d_in[3];
    const float* w2 = (const float*)d_in[4];
    float* out = (float*)d_out;

    __nv_bfloat16 *xh, *xl, *w1h, *w1l, *w3h, *w3l, *w2h, *w2l;
    cudaGetSymbolAddress((void**)&xh,  g_xh);  cudaGetSymbolAddress((void**)&xl,  g_xl);
    cudaGetSymbolAddress((void**)&w1h, g_w1h); cudaGetSymbolAddress((void**)&w1l, g_w1l);
    cudaGetSymbolAddress((void**)&w3h, g_w3h); cudaGetSymbolAddress((void**)&w3l, g_w3l);
    cudaGetSymbolAddress((void**)&w2h, g_w2h); cudaGetSymbolAddress((void**)&w2l, g_w2l);

    cudaFuncSetAttribute(ffn1_mma, cudaFuncAttributeMaxDynamicSharedMemorySize, SMEM_TOTAL);
    cudaFuncSetAttribute(ffn2_mma, cudaFuncAttributeMaxDynamicSharedMemorySize, SMEM_TOTAL);

    init_kernel<<<1, 32>>>();
    router_kernel<<<NTOK / 8, 256>>>(x, gw);

    int xn4 = NTOK * DIMD / 4;
    int wn4 = (int)(WN / 4);
    cvt_kernel<<<(xn4 + 255) / 256, 256>>>(x,  xh,  xl,  xn4);
    cvt_kernel<<<(wn4 + 255) / 256, 256>>>(w1, w1h, w1l, wn4);
    cvt_kernel<<<(wn4 + 255) / 256, 256>>>(w3, w3h, w3l, wn4);
    cvt_kernel<<<(wn4 + 255) / 256, 256>>>(w2, w2h, w2l, wn4);

    ffn1_mma<<<dim3(HID / 128, NTOK / 128, NEXP), 256, SMEM_TOTAL>>>();
    ffn2_mma<<<dim3(DIMD / 256, NTOK / 128, NEXP), 256, SMEM_TOTAL>>>();
    combine_kernel<<<(NTOK * (DIMD / 4) + 255) / 256, 256>>>(out);
}